// round 1
// baseline (speedup 1.0000x reference)
#include <cuda_runtime.h>
#include <cstdint>

// SoftPixelCNN fused kernel for B200 (sm_100a).
// One warp per vertex. Lane k computes the 9 offset weights for neighbor k
// (offsets are origin + +/- unit axes; derived analytically, matching the
// numpy meshgrid('xy') ordering of the reference OFFSETS table).
// Accumulation: lane owns features {2*lane, 2*lane+1} as a packed f32x2 pair;
// weights are staged duplicated in SMEM so fma.rn.f32x2 consumes them directly.

#define FULLMASK 0xFFFFFFFFu

__global__ __launch_bounds__(256)
void spcnn_kernel(const float* __restrict__ coords,   // (V,4)
                  const float* __restrict__ feats,    // (V,64)
                  const int*   __restrict__ nbr,      // (V,32)
                  const float* __restrict__ ls,       // (1,)
                  float*       __restrict__ out,      // (V,576)
                  int V)
{
    const int warp = threadIdx.x >> 5;
    const int lane = threadIdx.x & 31;
    const int v = blockIdx.x * 8 + warp;

    // Per-warp weight staging: 32 k-rows of 9 duplicated-pair weights
    // (18 floats), padded to 20 floats (80 B) for 16-byte alignment.
    __shared__ __align__(16) float ws[8][32][20];

    if (v >= V) return;

    const float g = 10.0f * ls[0];

    // ---------------- Phase 1: lane k -> weights for neighbor k ----------------
    const int idx = nbr[v * 32 + lane];
    const float4 cv = ((const float4*)coords)[v];
    const float4 cn = ((const float4*)coords)[idx];
    const float dx = cv.x - cn.x;
    const float dy = cv.y - cn.y;
    const float dz = cv.z - cn.z;
    const float dw = cv.w - cn.w;
    const float base = dx*dx + dy*dy + dz*dz + dw*dw;
    const float b1 = base + 1.0f;

    // OFFSETS order (verified against meshgrid 'xy' flatten order):
    // o0=(0,0,0,0) o1=(0,-1,0,0) o2=(-1,0,0,0) o3=(0,0,-1,0) o4=(0,0,0,-1)
    // o5=(0,0,0,1) o6=(0,0,1,0)  o7=(1,0,0,0)  o8=(0,1,0,0)
    float w[9];
    w[0] = __expf(-g * base);
    w[1] = __expf(-g * (b1 - 2.0f * dy));
    w[2] = __expf(-g * (b1 - 2.0f * dx));
    w[3] = __expf(-g * (b1 - 2.0f * dz));
    w[4] = __expf(-g * (b1 - 2.0f * dw));
    w[5] = __expf(-g * (b1 + 2.0f * dw));
    w[6] = __expf(-g * (b1 + 2.0f * dz));
    w[7] = __expf(-g * (b1 + 2.0f * dx));
    w[8] = __expf(-g * (b1 + 2.0f * dy));

    {
        float2* wr = (float2*)ws[warp][lane];
        #pragma unroll
        for (int o = 0; o < 9; ++o)
            wr[o] = make_float2(w[o], w[o]);
    }
    __syncwarp();

    // ---------------- Phase 2: accumulate 9 offsets x 2 features ----------------
    unsigned long long acc[9];
    #pragma unroll
    for (int o = 0; o < 9; ++o) acc[o] = 0ull;  // (0.0f, 0.0f)

    const char* wbase = (const char*)ws[warp];

    #pragma unroll 8
    for (int k = 0; k < 32; ++k) {
        const int n = __shfl_sync(FULLMASK, idx, k);
        // coalesced 256B/warp gather of neighbor n's feature row
        const unsigned long long gp =
            *(const unsigned long long*)(feats + (size_t)n * 64 + lane * 2);

        const ulonglong2* wq = (const ulonglong2*)(wbase + k * 80);
        const ulonglong2 q0 = wq[0];   // (w0,w0),(w1,w1)
        const ulonglong2 q1 = wq[1];   // (w2,w2),(w3,w3)
        const ulonglong2 q2 = wq[2];   // (w4,w4),(w5,w5)
        const ulonglong2 q3 = wq[3];   // (w6,w6),(w7,w7)
        const unsigned long long q8 =
            ((const unsigned long long*)(wbase + k * 80))[8];  // (w8,w8)

        asm("fma.rn.f32x2 %0, %1, %2, %0;" : "+l"(acc[0]) : "l"(q0.x), "l"(gp));
        asm("fma.rn.f32x2 %0, %1, %2, %0;" : "+l"(acc[1]) : "l"(q0.y), "l"(gp));
        asm("fma.rn.f32x2 %0, %1, %2, %0;" : "+l"(acc[2]) : "l"(q1.x), "l"(gp));
        asm("fma.rn.f32x2 %0, %1, %2, %0;" : "+l"(acc[3]) : "l"(q1.y), "l"(gp));
        asm("fma.rn.f32x2 %0, %1, %2, %0;" : "+l"(acc[4]) : "l"(q2.x), "l"(gp));
        asm("fma.rn.f32x2 %0, %1, %2, %0;" : "+l"(acc[5]) : "l"(q2.y), "l"(gp));
        asm("fma.rn.f32x2 %0, %1, %2, %0;" : "+l"(acc[6]) : "l"(q3.x), "l"(gp));
        asm("fma.rn.f32x2 %0, %1, %2, %0;" : "+l"(acc[7]) : "l"(q3.y), "l"(gp));
        asm("fma.rn.f32x2 %0, %1, %2, %0;" : "+l"(acc[8]) : "l"(q8),   "l"(gp));
    }

    // ---------------- Epilogue: mean over K=32, store (v, o*64 + 2*lane) --------
    const unsigned long long inv32 = 0x3D0000003D000000ull;  // (1/32, 1/32)
    float* orow = out + (size_t)v * 576 + lane * 2;
    #pragma unroll
    for (int o = 0; o < 9; ++o) {
        unsigned long long r;
        asm("mul.rn.f32x2 %0, %1, %2;" : "=l"(r) : "l"(acc[o]), "l"(inv32));
        *(unsigned long long*)(orow + o * 64) = r;
    }
}

extern "C" void kernel_launch(void* const* d_in, const int* in_sizes, int n_in,
                              void* d_out, int out_size)
{
    // metadata order: coordinates(V*4), features(V*64), distsq(V*32 unused),
    //                 neighbour_indices(V*32 int32), length_scale(1)
    const float* coords = (const float*)d_in[0];
    const float* feats  = (const float*)d_in[1];
    const int*   nbr    = (const int*)  d_in[3];
    const float* ls     = (const float*)d_in[4];
    float* out = (float*)d_out;

    const int V = in_sizes[0] / 4;
    const int blocks = (V + 7) / 8;   // 8 warps (vertices) per 256-thread block
    spcnn_kernel<<<blocks, 256>>>(coords, feats, nbr, ls, out, V);
}

// round 2
// speedup vs baseline: 1.2245x; 1.2245x over previous
#include <cuda_runtime.h>
#include <cstdint>

// SoftPixelCNN fused kernel, R2: half-warp K-split + unduplicated weight staging.
// One warp per vertex.
//   Phase 1: lane k computes the 9 offset weights for neighbor k, stores them
//            UNduplicated (9 floats) in SMEM.
//   Phase 2: lanes 0-15 ("half A") process even k, lanes 16-31 ("half B") odd k.
//            Each half-lane owns 4 features (16 lanes x 4 = all 64 features),
//            accumulating 9 offsets x 2 f32x2 pairs. Weight fan-out per value is
//            16 lanes (not 32), halving L1 return traffic for weights; the
//            unduplicated layout halves it again. (w,w) pairs are built with
//            register packs (ALU) instead of duplicated LDS.
//   Merge:   half B dumps its partials through a 2304B SMEM buffer; half A adds,
//            applies 1/K, and stores.

#define FULLMASK 0xFFFFFFFFu
typedef unsigned long long u64;

__global__ __launch_bounds__(256)
void spcnn_kernel(const float* __restrict__ coords,   // (V,4)
                  const float* __restrict__ feats,    // (V,64)
                  const int*   __restrict__ nbr,      // (V,32)
                  const float* __restrict__ ls,       // (1,)
                  float*       __restrict__ out,      // (V,576)
                  int V)
{
    const int warp = threadIdx.x >> 5;
    const int lane = threadIdx.x & 31;
    const int hb   = lane >> 4;          // 0 = half A (even k), 1 = half B (odd k)
    const int hl   = lane & 15;          // lane within half
    const int v    = blockIdx.x * 8 + warp;

    // Per-warp scratch: 2304 B. During the loop: weight rows ws[k][12] floats
    // (first 1536 B). After the loop (post __syncwarp): merge buffer
    // buf[o][64] floats (full 2304 B), overlaying the weights.
    __shared__ __align__(16) float scratch[8][576];

    if (v >= V) return;

    float* wbuf = scratch[warp];
    const float g = 10.0f * ls[0];

    // ---------------- Phase 1: lane k -> 9 weights for neighbor k --------------
    const int idx = nbr[v * 32 + lane];
    const float4 cv = ((const float4*)coords)[v];
    const float4 cn = ((const float4*)coords)[idx];
    const float dx = cv.x - cn.x;
    const float dy = cv.y - cn.y;
    const float dz = cv.z - cn.z;
    const float dw = cv.w - cn.w;
    const float base = dx*dx + dy*dy + dz*dz + dw*dw;
    const float b1 = base + 1.0f;

    // OFFSETS order (verified in R1, rel_err 8e-7):
    // o0=0, o1=-y, o2=-x, o3=-z, o4=-w, o5=+w, o6=+z, o7=+x, o8=+y
    float w0 = __expf(-g * base);
    float w1 = __expf(-g * (b1 - 2.0f * dy));
    float w2 = __expf(-g * (b1 - 2.0f * dx));
    float w3 = __expf(-g * (b1 - 2.0f * dz));
    float w4 = __expf(-g * (b1 - 2.0f * dw));
    float w5 = __expf(-g * (b1 + 2.0f * dw));
    float w6 = __expf(-g * (b1 + 2.0f * dz));
    float w7 = __expf(-g * (b1 + 2.0f * dx));
    float w8 = __expf(-g * (b1 + 2.0f * dy));

    {
        float* wr = wbuf + lane * 12;          // 48 B row, unduplicated
        ((float4*)wr)[0] = make_float4(w0, w1, w2, w3);
        ((float4*)wr)[1] = make_float4(w4, w5, w6, w7);
        wr[8] = w8;
    }
    __syncwarp();

    // ---------------- Phase 2: half-warp split over k ---------------------------
    // acc[o][p]: offset o, feature pair p (p=0 -> features fc,fc+1; p=1 -> fc+2,fc+3)
    u64 acc[9][2];
    #pragma unroll
    for (int o = 0; o < 9; ++o) { acc[o][0] = 0ull; acc[o][1] = 0ull; }

    const int fc = hl * 4;                      // feature column base (0..60)

    #pragma unroll 4
    for (int i = 0; i < 16; ++i) {
        const int kk = 2 * i + hb;              // this half's k
        const int n  = __shfl_sync(FULLMASK, idx, kk);

        // 16 B coalesced-per-half feature load: lanes of a half cover 256 B of row n
        const ulonglong2 fp = *(const ulonglong2*)(feats + (size_t)n * 64 + fc);

        const float* wr = wbuf + kk * 12;
        const float4 wa = ((const float4*)wr)[0];   // w0..w3
        const float4 wb = ((const float4*)wr)[1];   // w4..w7
        const float  wc = wr[8];                    // w8

        u64 wp[9];
        asm("mov.b64 %0, {%1,%1};" : "=l"(wp[0]) : "f"(wa.x));
        asm("mov.b64 %0, {%1,%1};" : "=l"(wp[1]) : "f"(wa.y));
        asm("mov.b64 %0, {%1,%1};" : "=l"(wp[2]) : "f"(wa.z));
        asm("mov.b64 %0, {%1,%1};" : "=l"(wp[3]) : "f"(wa.w));
        asm("mov.b64 %0, {%1,%1};" : "=l"(wp[4]) : "f"(wb.x));
        asm("mov.b64 %0, {%1,%1};" : "=l"(wp[5]) : "f"(wb.y));
        asm("mov.b64 %0, {%1,%1};" : "=l"(wp[6]) : "f"(wb.z));
        asm("mov.b64 %0, {%1,%1};" : "=l"(wp[7]) : "f"(wb.w));
        asm("mov.b64 %0, {%1,%1};" : "=l"(wp[8]) : "f"(wc));

        #pragma unroll
        for (int o = 0; o < 9; ++o) {
            asm("fma.rn.f32x2 %0, %1, %2, %0;" : "+l"(acc[o][0]) : "l"(wp[o]), "l"(fp.x));
            asm("fma.rn.f32x2 %0, %1, %2, %0;" : "+l"(acc[o][1]) : "l"(wp[o]), "l"(fp.y));
        }
    }

    // ---------------- Merge halves via SMEM (reuses weight area) ---------------
    __syncwarp();
    if (hb) {
        // half B: deposit partials, conflict-free (16 lanes x contiguous 16 B)
        #pragma unroll
        for (int o = 0; o < 9; ++o) {
            ulonglong2 st; st.x = acc[o][0]; st.y = acc[o][1];
            *(ulonglong2*)(wbuf + o * 64 + fc) = st;
        }
    }
    __syncwarp();
    if (!hb) {
        const u64 inv32 = 0x3D0000003D000000ull;  // (1/32, 1/32)
        float* orow = out + (size_t)v * 576 + fc;
        #pragma unroll
        for (int o = 0; o < 9; ++o) {
            const ulonglong2 other = *(const ulonglong2*)(wbuf + o * 64 + fc);
            u64 s0, s1, r0, r1;
            asm("add.rn.f32x2 %0, %1, %2;" : "=l"(s0) : "l"(acc[o][0]), "l"(other.x));
            asm("add.rn.f32x2 %0, %1, %2;" : "=l"(s1) : "l"(acc[o][1]), "l"(other.y));
            asm("mul.rn.f32x2 %0, %1, %2;" : "=l"(r0) : "l"(s0), "l"(inv32));
            asm("mul.rn.f32x2 %0, %1, %2;" : "=l"(r1) : "l"(s1), "l"(inv32));
            ulonglong2 st; st.x = r0; st.y = r1;
            *(ulonglong2*)(orow + o * 64) = st;
        }
    }
}

extern "C" void kernel_launch(void* const* d_in, const int* in_sizes, int n_in,
                              void* d_out, int out_size)
{
    const float* coords = (const float*)d_in[0];
    const float* feats  = (const float*)d_in[1];
    const int*   nbr    = (const int*)  d_in[3];
    const float* ls     = (const float*)d_in[4];
    float* out = (float*)d_out;

    const int V = in_sizes[0] / 4;
    const int blocks = (V + 7) / 8;
    spcnn_kernel<<<blocks, 256>>>(coords, feats, nbr, ls, out, V);
}

// round 3
// speedup vs baseline: 1.3770x; 1.1245x over previous
#include <cuda_runtime.h>
#include <cstdint>

// SoftPixelCNN R3: offset-paired f32x2 accumulation + SMEM index staging +
// forced occupancy.
// One warp per vertex; lanes 0-15 process even k, lanes 16-31 odd k; each
// half-lane owns 4 features. Accumulators are (offset o, offset o+1) f32x2
// pairs so LDS.128 of the weight row feeds FFMA2 directly (no weight packs);
// only the 4 feature scalars are duplicated into (f,f) pairs (4 packs/k).
// Neighbor indices staged in SMEM (LDS.128 per 4 iterations) - no SHFL in loop.

#define FULLMASK 0xFFFFFFFFu
typedef unsigned long long u64;

__global__ __launch_bounds__(256, 4)
void spcnn_kernel(const float* __restrict__ coords,   // (V,4)
                  const float* __restrict__ feats,    // (V,64)
                  const int*   __restrict__ nbr,      // (V,32)
                  const float* __restrict__ ls,       // (1,)
                  float*       __restrict__ out,      // (V,576)
                  int V)
{
    const int warp = threadIdx.x >> 5;
    const int lane = threadIdx.x & 31;
    const int hb   = lane >> 4;          // 0: even k, 1: odd k
    const int hl   = lane & 15;
    const int v    = blockIdx.x * 8 + warp;

    // Per-warp scratch, 2304 B (overlaid):
    //   loop phase : weights [0,1536) = 32 rows x 12 floats ; idx [1536,1664)
    //   merge phase: pair buffer [0,2304)
    __shared__ __align__(16) float scratch[8][576];

    if (v >= V) return;

    float* wbuf = scratch[warp];
    int*   ibuf = (int*)(wbuf + 384);     // 32 ints at byte 1536
    const float g = 10.0f * ls[0];

    // ---------------- Phase 1: lane k -> 9 weights + staged index --------------
    const int idx = nbr[v * 32 + lane];
    const float4 cv = ((const float4*)coords)[v];
    const float4 cn = ((const float4*)coords)[idx];
    const float dx = cv.x - cn.x;
    const float dy = cv.y - cn.y;
    const float dz = cv.z - cn.z;
    const float dw = cv.w - cn.w;
    const float base = dx*dx + dy*dy + dz*dz + dw*dw;
    const float b1 = base + 1.0f;

    // OFFSETS (verified R1): o0=0 o1=-y o2=-x o3=-z o4=-w o5=+w o6=+z o7=+x o8=+y
    const float w0 = __expf(-g * base);
    const float w1 = __expf(-g * (b1 - 2.0f * dy));
    const float w2 = __expf(-g * (b1 - 2.0f * dx));
    const float w3 = __expf(-g * (b1 - 2.0f * dz));
    const float w4 = __expf(-g * (b1 - 2.0f * dw));
    const float w5 = __expf(-g * (b1 + 2.0f * dw));
    const float w6 = __expf(-g * (b1 + 2.0f * dz));
    const float w7 = __expf(-g * (b1 + 2.0f * dx));
    const float w8 = __expf(-g * (b1 + 2.0f * dy));

    {
        float* wr = wbuf + lane * 12;                  // 48 B rows, 16B aligned
        ((float4*)wr)[0] = make_float4(w0, w1, w2, w3);
        ((float4*)wr)[1] = make_float4(w4, w5, w6, w7);
        wr[8] = w8;
        // de-interleave indices by half: half hb's i-th k at ibuf[hb*16+i]
        ibuf[(lane & 1) * 16 + (lane >> 1)] = idx;
    }
    __syncwarp();

    // ---------------- Phase 2: half-split loop, offset-pair accumulators --------
    // accp[op][j]: offsets (2op, 2op+1), feature fc+j.  acc8[j]: offset 8.
    u64   accp[4][4];
    float acc8[4];
    #pragma unroll
    for (int op = 0; op < 4; ++op)
        #pragma unroll
        for (int j = 0; j < 4; ++j) accp[op][j] = 0ull;
    #pragma unroll
    for (int j = 0; j < 4; ++j) acc8[j] = 0.0f;

    const int fc = hl * 4;
    const int4* igrp = (const int4*)(ibuf + hb * 16);

    #pragma unroll
    for (int jg = 0; jg < 4; ++jg) {
        const int4 i4 = igrp[jg];                      // 4 neighbor indices
        const int ns[4] = { i4.x, i4.y, i4.z, i4.w };

        #pragma unroll
        for (int t = 0; t < 4; ++t) {
            const int kk = (jg * 4 + t) * 2 + hb;
            const int n  = ns[t];

            const float4 fv = *(const float4*)(feats + (size_t)n * 64 + fc);

            const float* wr = wbuf + kk * 12;
            const ulonglong2 wA = ((const ulonglong2*)wr)[0]; // (w0,w1),(w2,w3)
            const ulonglong2 wB = ((const ulonglong2*)wr)[1]; // (w4,w5),(w6,w7)
            const float     w8k = wr[8];

            u64 fp[4];
            asm("mov.b64 %0, {%1,%1};" : "=l"(fp[0]) : "f"(fv.x));
            asm("mov.b64 %0, {%1,%1};" : "=l"(fp[1]) : "f"(fv.y));
            asm("mov.b64 %0, {%1,%1};" : "=l"(fp[2]) : "f"(fv.z));
            asm("mov.b64 %0, {%1,%1};" : "=l"(fp[3]) : "f"(fv.w));

            #pragma unroll
            for (int j = 0; j < 4; ++j) {
                asm("fma.rn.f32x2 %0, %1, %2, %0;" : "+l"(accp[0][j]) : "l"(wA.x), "l"(fp[j]));
                asm("fma.rn.f32x2 %0, %1, %2, %0;" : "+l"(accp[1][j]) : "l"(wA.y), "l"(fp[j]));
                asm("fma.rn.f32x2 %0, %1, %2, %0;" : "+l"(accp[2][j]) : "l"(wB.x), "l"(fp[j]));
                asm("fma.rn.f32x2 %0, %1, %2, %0;" : "+l"(accp[3][j]) : "l"(wB.y), "l"(fp[j]));
            }
            acc8[0] = fmaf(w8k, fv.x, acc8[0]);
            acc8[1] = fmaf(w8k, fv.y, acc8[1]);
            acc8[2] = fmaf(w8k, fv.z, acc8[2]);
            acc8[3] = fmaf(w8k, fv.w, acc8[3]);
        }
    }

    // ---------------- Merge halves (overlays weight/idx region) ----------------
    __syncwarp();
    char* pb = (char*)wbuf;
    if (hb) {
        #pragma unroll
        for (int op = 0; op < 4; ++op) {
            ulonglong2 s0; s0.x = accp[op][0]; s0.y = accp[op][1];
            ulonglong2 s1; s1.x = accp[op][2]; s1.y = accp[op][3];
            *(ulonglong2*)(pb + op * 512 + hl * 32)      = s0;
            *(ulonglong2*)(pb + op * 512 + hl * 32 + 16) = s1;
        }
        *(float4*)(pb + 2048 + hl * 16) = make_float4(acc8[0], acc8[1], acc8[2], acc8[3]);
    }
    __syncwarp();
    if (!hb) {
        const u64 inv32p = 0x3D0000003D000000ull;   // (1/32, 1/32)
        const float inv32 = 0.03125f;
        float* orow = out + (size_t)v * 576 + fc;

        #pragma unroll
        for (int op = 0; op < 4; ++op) {
            const ulonglong2 t0 = *(const ulonglong2*)(pb + op * 512 + hl * 32);
            const ulonglong2 t1 = *(const ulonglong2*)(pb + op * 512 + hl * 32 + 16);
            u64 m[4];
            asm("add.rn.f32x2 %0, %1, %2;" : "=l"(m[0]) : "l"(accp[op][0]), "l"(t0.x));
            asm("add.rn.f32x2 %0, %1, %2;" : "=l"(m[1]) : "l"(accp[op][1]), "l"(t0.y));
            asm("add.rn.f32x2 %0, %1, %2;" : "=l"(m[2]) : "l"(accp[op][2]), "l"(t1.x));
            asm("add.rn.f32x2 %0, %1, %2;" : "=l"(m[3]) : "l"(accp[op][3]), "l"(t1.y));
            #pragma unroll
            for (int j = 0; j < 4; ++j)
                asm("mul.rn.f32x2 %0, %0, %1;" : "+l"(m[j]) : "l"(inv32p));

            // de-interleave: lo halves -> offset 2op, hi halves -> offset 2op+1
            float2 e0 = *(float2*)&m[0], e1 = *(float2*)&m[1];
            float2 e2 = *(float2*)&m[2], e3 = *(float2*)&m[3];
            *(float4*)(orow + (2 * op)     * 64) = make_float4(e0.x, e1.x, e2.x, e3.x);
            *(float4*)(orow + (2 * op + 1) * 64) = make_float4(e0.y, e1.y, e2.y, e3.y);
        }
        const float4 b8 = *(const float4*)(pb + 2048 + hl * 16);
        *(float4*)(orow + 8 * 64) = make_float4((acc8[0] + b8.x) * inv32,
                                                (acc8[1] + b8.y) * inv32,
                                                (acc8[2] + b8.z) * inv32,
                                                (acc8[3] + b8.w) * inv32);
    }
}

extern "C" void kernel_launch(void* const* d_in, const int* in_sizes, int n_in,
                              void* d_out, int out_size)
{
    const float* coords = (const float*)d_in[0];
    const float* feats  = (const float*)d_in[1];
    const int*   nbr    = (const int*)  d_in[3];
    const float* ls     = (const float*)d_in[4];
    float* out = (float*)d_out;

    const int V = in_sizes[0] / 4;
    const int blocks = (V + 7) / 8;
    spcnn_kernel<<<blocks, 256>>>(coords, feats, nbr, ls, out, V);
}

// round 4
// speedup vs baseline: 1.5702x; 1.1403x over previous
#include <cuda_runtime.h>
#include <cstdint>

// SoftPixelCNN R4: two vertices per warp -> no merge phase.
// Lanes 0-15 own vertex A, lanes 16-31 vertex B. Each half sweeps all K=32
// neighbors with 4 features per lane (16 lanes x 4 = 64 features), storing
// results straight from registers. Weights per k stored as 8 floats (2x
// LDS.128, consumed as (w,w+1) u64 pairs by fma.rn.f32x2); w8 batched in a
// separate array read as float4 per 4 iterations; indices batched as int4.

typedef unsigned long long u64;

__global__ __launch_bounds__(256, 4)
void spcnn_kernel(const float* __restrict__ coords,   // (V,4)
                  const float* __restrict__ feats,    // (V,64)
                  const int*   __restrict__ nbr,      // (V,32)
                  const float* __restrict__ ls,       // (1,)
                  float*       __restrict__ out,      // (V,576)
                  int V)
{
    const int warp = threadIdx.x >> 5;
    const int lane = threadIdx.x & 31;
    const int hb   = lane >> 4;          // which vertex this half owns
    const int hl   = lane & 15;
    const int vbase = (blockIdx.x * 8 + warp) * 2;

    struct WarpScratch {
        float w07[2][32][8];   // 2048 B: weights w0..w7 per (vertex, k)
        float w8a[2][32];      // 256 B : w8 per (vertex, k)
        int   ib [2][32];      // 256 B : neighbor indices
    };
    __shared__ __align__(16) WarpScratch ws[8];
    WarpScratch& S = ws[warp];

    if (vbase >= V) return;
    const float g = 10.0f * ls[0];

    // ---------------- Phase 1: each lane fills weights for both vertices -------
    #pragma unroll
    for (int s = 0; s < 2; ++s) {
        const int v = vbase + s;
        if (v >= V) break;
        const int idx = nbr[v * 32 + lane];
        const float4 cv = ((const float4*)coords)[v];
        const float4 cn = ((const float4*)coords)[idx];
        const float dx = cv.x - cn.x;
        const float dy = cv.y - cn.y;
        const float dz = cv.z - cn.z;
        const float dw = cv.w - cn.w;
        const float base = dx*dx + dy*dy + dz*dz + dw*dw;
        const float b1 = base + 1.0f;

        // OFFSETS (verified R1): o0=0 o1=-y o2=-x o3=-z o4=-w o5=+w o6=+z o7=+x o8=+y
        const float w0 = __expf(-g * base);
        const float w1 = __expf(-g * (b1 - 2.0f * dy));
        const float w2 = __expf(-g * (b1 - 2.0f * dx));
        const float w3 = __expf(-g * (b1 - 2.0f * dz));
        const float w4 = __expf(-g * (b1 - 2.0f * dw));
        const float w5 = __expf(-g * (b1 + 2.0f * dw));
        const float w6 = __expf(-g * (b1 + 2.0f * dz));
        const float w7 = __expf(-g * (b1 + 2.0f * dx));
        const float w8 = __expf(-g * (b1 + 2.0f * dy));

        float* wr = S.w07[s][lane];
        ((float4*)wr)[0] = make_float4(w0, w1, w2, w3);
        ((float4*)wr)[1] = make_float4(w4, w5, w6, w7);
        S.w8a[s][lane] = w8;
        S.ib [s][lane] = idx;
    }
    __syncwarp();

    // ---------------- Phase 2: each half sweeps its vertex's 32 neighbors -------
    const int v = vbase + hb;
    if (v >= V) return;                  // no further syncs below; safe exit

    u64   accp[4][4];                    // (offset 2op, 2op+1) x feature j
    float acc8[4];
    #pragma unroll
    for (int op = 0; op < 4; ++op)
        #pragma unroll
        for (int j = 0; j < 4; ++j) accp[op][j] = 0ull;
    #pragma unroll
    for (int j = 0; j < 4; ++j) acc8[j] = 0.0f;

    const int fc = hl * 4;

    #pragma unroll
    for (int gq = 0; gq < 8; ++gq) {
        const int4   i4  = *(const int4*)  &S.ib [hb][gq * 4];
        const float4 w8v = *(const float4*)&S.w8a[hb][gq * 4];
        const int   ns[4] = { i4.x, i4.y, i4.z, i4.w };
        const float w8s[4] = { w8v.x, w8v.y, w8v.z, w8v.w };

        #pragma unroll
        for (int t = 0; t < 4; ++t) {
            const int k = gq * 4 + t;
            const float4 fv = *(const float4*)(feats + (size_t)ns[t] * 64 + fc);

            const ulonglong2* wr = (const ulonglong2*)S.w07[hb][k];
            const ulonglong2 wA = wr[0];   // (w0,w1),(w2,w3)
            const ulonglong2 wB = wr[1];   // (w4,w5),(w6,w7)

            u64 fp[4];
            asm("mov.b64 %0, {%1,%1};" : "=l"(fp[0]) : "f"(fv.x));
            asm("mov.b64 %0, {%1,%1};" : "=l"(fp[1]) : "f"(fv.y));
            asm("mov.b64 %0, {%1,%1};" : "=l"(fp[2]) : "f"(fv.z));
            asm("mov.b64 %0, {%1,%1};" : "=l"(fp[3]) : "f"(fv.w));

            #pragma unroll
            for (int j = 0; j < 4; ++j) {
                asm("fma.rn.f32x2 %0, %1, %2, %0;" : "+l"(accp[0][j]) : "l"(wA.x), "l"(fp[j]));
                asm("fma.rn.f32x2 %0, %1, %2, %0;" : "+l"(accp[1][j]) : "l"(wA.y), "l"(fp[j]));
                asm("fma.rn.f32x2 %0, %1, %2, %0;" : "+l"(accp[2][j]) : "l"(wB.x), "l"(fp[j]));
                asm("fma.rn.f32x2 %0, %1, %2, %0;" : "+l"(accp[3][j]) : "l"(wB.y), "l"(fp[j]));
            }
            acc8[0] = fmaf(w8s[t], fv.x, acc8[0]);
            acc8[1] = fmaf(w8s[t], fv.y, acc8[1]);
            acc8[2] = fmaf(w8s[t], fv.z, acc8[2]);
            acc8[3] = fmaf(w8s[t], fv.w, acc8[3]);
        }
    }

    // ---------------- Epilogue: scale by 1/K, de-interleave, store --------------
    const u64   inv32p = 0x3D0000003D000000ull;   // (1/32, 1/32)
    const float inv32  = 0.03125f;
    float* orow = out + (size_t)v * 576 + fc;

    #pragma unroll
    for (int op = 0; op < 4; ++op) {
        #pragma unroll
        for (int j = 0; j < 4; ++j)
            asm("mul.rn.f32x2 %0, %0, %1;" : "+l"(accp[op][j]) : "l"(inv32p));
        const float2 e0 = *(float2*)&accp[op][0];
        const float2 e1 = *(float2*)&accp[op][1];
        const float2 e2 = *(float2*)&accp[op][2];
        const float2 e3 = *(float2*)&accp[op][3];
        *(float4*)(orow + (2 * op)     * 64) = make_float4(e0.x, e1.x, e2.x, e3.x);
        *(float4*)(orow + (2 * op + 1) * 64) = make_float4(e0.y, e1.y, e2.y, e3.y);
    }
    *(float4*)(orow + 8 * 64) = make_float4(acc8[0] * inv32, acc8[1] * inv32,
                                            acc8[2] * inv32, acc8[3] * inv32);
}

extern "C" void kernel_launch(void* const* d_in, const int* in_sizes, int n_in,
                              void* d_out, int out_size)
{
    const float* coords = (const float*)d_in[0];
    const float* feats  = (const float*)d_in[1];
    const int*   nbr    = (const int*)  d_in[3];
    const float* ls     = (const float*)d_in[4];
    float* out = (float*)d_out;

    const int V = in_sizes[0] / 4;
    const int verts_per_block = 16;   // 8 warps x 2 vertices
    const int blocks = (V + verts_per_block - 1) / verts_per_block;
    spcnn_kernel<<<blocks, 256>>>(coords, feats, nbr, ls, out, V);
}